// round 17
// baseline (speedup 1.0000x reference)
#include <cuda_runtime.h>
#include <cstdint>

// MultiLIF: I[B=32, L=2048, K=512] -> (spikes[B,L,K], spike_series[B,L,K])
// d_out: spikes (B*L*K floats) then spike_series.
//
// R17 vs R16 (92.2us):
//  1. Role flip: compute warps are now wid 4-7. B300 arbiter is hi-wid-first;
//     previously writer warps (wid 4-7) preempted the chain-critical
//     recurrence with 12-cyc STG.128 bursts. Now the serial chain has
//     priority and stores fill idle slots only.
//  2. Writers own n: running per-neuron count register across chunks
//     (exact integer adds == reference); sn checkpoint array and compute-side
//     n accumulation deleted.
// Same smem-staged input, bit-packed spikes, one textual barrier, 128x256.

static constexpr int B_ = 32;
static constexpr int L_ = 2048;
static constexpr int K_ = 512;
static constexpr int NPB = 128;              // neurons per block
static constexpr int CHUNK = 32;             // steps per chunk
static constexpr int NCH = L_ / CHUNK;       // 64 chunks
static constexpr int ITER = NCH + 2;         // 66 pipeline iterations

__device__ __forceinline__ float div_const_rn(float x, float b, float y)
{
    // Markstein: correctly-rounded RN(x/b), y = RN(1/b). Branch-free;
    // == __fdiv_rn for all values reachable here.
    float q0 = __fmul_rn(x, y);
    float r  = __fmaf_rn(-b, q0, x);
    return __fmaf_rn(r, y, q0);
}

__global__ __launch_bounds__(256, 1)
void lif_fused(const float* __restrict__ I,
               float* __restrict__ spikes,
               float* __restrict__ series)
{
    __shared__ float    sin_[2][CHUNK][NPB]; // 32 KB input tiles
    __shared__ uint32_t sbits[2][NPB];       // spike bits per chunk

    const int tid = threadIdx.x;
    const int bid = blockIdx.x;
    const bool is_compute = (tid >= NPB);    // wid 4-7: HIGH arbiter priority
    const int  cid = tid - NPB;              // compute neuron-in-block

    const int b_blk = (bid * NPB) >> 9;
    const int kbase = (bid * NPB) & (K_ - 1);
    const int64_t in_base = (int64_t)b_blk * L_ * K_ + kbase;

    // ---------------- compute state ----------------
    const float c2 = -0.5f - div_const_rn(-0.5f, 20.0f, 0.05f);
    float uv = 0.0f, a = 0.0f;
    bool fire = false;

    // ---------------- writer constants/state (wid 0-3) ----------------
    const int w    = tid & (NPB - 1);        // writer index 0..127
    const int tgrp = w >> 5;                 // 8-step subrange 0..3
    const int nb   = (w & 31) * 4;           // first of 4 owned local neurons
    const int gn   = bid * NPB + nb;
    const int wb   = gn >> 9;
    const int wk   = gn & (K_ - 1);
    const int s4   = K_ / 4;                 // float4 stride per timestep
    const uint32_t premask = (tgrp == 0) ? 0u : ((1u << (tgrp * 8)) - 1u);
    const int sh = tgrp * 8;
    float4 nacc = {0.f, 0.f, 0.f, 0.f};      // running n per owned neuron

#pragma unroll 1
    for (int i = 0; i < ITER; i++) {
        if (is_compute) {
            if (i >= 1 && i <= NCH) {
                int slot = (i - 1) & 1;
                uint32_t bits = 0;
#pragma unroll
                for (int u = 0; u < CHUNK; u++) {
                    float It = sin_[slot][u][cid];
                    float th = 1.0f + 1.5f * a;
                    float uA = (uv - div_const_rn(uv, 20.0f, 0.05f)) + It;
                    float uB = c2 + It;
                    float un = fire ? uB : uA;
                    bool f = (un >= th);
                    float s = f ? 1.0f : 0.0f;
                    bits |= (f ? 1u : 0u) << u;       // compile-time position
                    a = (a - div_const_rn(a, 100.0f, 0.01f)) + s;
                    uv = un; fire = f;
                }
                sbits[slot][cid] = bits;
            }
        } else {
            // (a) issue input loads for chunk i (latency overlapped by (b))
            float4 vdat[8];
            if (i < NCH) {
                int t0 = i * CHUNK;
#pragma unroll
                for (int j = 0; j < 8; j++) {
                    int flat4 = j * NPB + w;          // float4 index in tile
                    int step  = flat4 >> 5;           // 32 float4 per step
                    int col4  = flat4 & 31;
                    vdat[j] = __ldcs((const float4*)
                        (I + in_base + (int64_t)(t0 + step) * K_) + col4);
                }
            }
            // (b) store outputs for chunk i-2; maintain running n
            if (i >= 2) {
                int c = i - 2;
                int slot = c & 1;
                uint4 W = *(const uint4*)&sbits[slot][nb];

                float4 n4;   // n at the start of this thread's 8-step window
                n4.x = nacc.x + (float)__popc(W.x & premask);
                n4.y = nacc.y + (float)__popc(W.y & premask);
                n4.z = nacc.z + (float)__popc(W.z & premask);
                n4.w = nacc.w + (float)__popc(W.w & premask);

                int t0c = c * CHUNK + tgrp * 8;
                int64_t base = ((int64_t)wb * L_ + t0c) * K_ + wk;
                float4* sp = (float4*)(spikes + base);
                float4* np = (float4*)(series + base);
#pragma unroll
                for (int u = 0; u < 8; u++) {
                    float4 s;
                    s.x = ((W.x >> (sh + u)) & 1u) ? 1.0f : 0.0f;
                    s.y = ((W.y >> (sh + u)) & 1u) ? 1.0f : 0.0f;
                    s.z = ((W.z >> (sh + u)) & 1u) ? 1.0f : 0.0f;
                    s.w = ((W.w >> (sh + u)) & 1u) ? 1.0f : 0.0f;
                    n4.x += s.x; n4.y += s.y; n4.z += s.z; n4.w += s.w;
                    __stcs(sp + u * s4, s);
                    __stcs(np + u * s4, n4);
                }
                // advance running count past the whole chunk (exact ints)
                nacc.x += (float)__popc(W.x);
                nacc.y += (float)__popc(W.y);
                nacc.z += (float)__popc(W.z);
                nacc.w += (float)__popc(W.w);
            }
            // (c) deposit loaded input into smem tile
            if (i < NCH) {
                int islot = i & 1;
#pragma unroll
                for (int j = 0; j < 8; j++) {
                    int flat4 = j * NPB + w;
                    int step  = flat4 >> 5;
                    int col4  = flat4 & 31;
                    *(float4*)&sin_[islot][step][col4 * 4] = vdat[j];
                }
            }
        }
        __syncthreads();   // single textual barrier, ITER arrivals/thread
    }
}

extern "C" void kernel_launch(void* const* d_in, const int* in_sizes, int n_in,
                              void* d_out, int out_size)
{
    const float* I = (const float*)d_in[0];
    float* spikes = (float*)d_out;
    float* series = (float*)d_out + (int64_t)B_ * L_ * K_;

    lif_fused<<<128, 256>>>(I, spikes, series);
}